// round 1
// baseline (speedup 1.0000x reference)
#include <cuda_runtime.h>

#define BB 4
#define SS 1024
#define DD 768
#define HH 12
#define HDD 64

// ---------------- device scratch (allocation-free: __device__ globals) -------
__device__ float g_qf[BB * SS * DD];    // q projection, flat [B,S,768]
__device__ float g_kf[BB * SS * DD];    // k projection
__device__ float g_vf[BB * SS * DD];    // v projection
__device__ float g_ctx[BB * SS * DD];   // attention output before final proj
__device__ float g_L0[BB * HH * SS * SS];  // raw per-head logits  (192 MB)
__device__ float g_A [BB * HH * SS * SS];  // mixed attention       (192 MB)

// ---------------- FFMA-only exp (avoids MUFU.EX2 throughput wall) ------------
__device__ __forceinline__ float fexp(float x) {
    // x <= 0 always here (softmax shifted by rowmax); clamp for safety.
    float t = fmaxf(x * 1.4426950408889634f, -126.0f);
    float fi = floorf(t);
    float f = t - fi;               // f in [0,1)
    // degree-6 Taylor of 2^f = e^{f ln2}; max rel err ~1.7e-5
    float p = 1.5403530e-4f;
    p = fmaf(p, f, 1.3333558e-3f);
    p = fmaf(p, f, 9.6181291e-3f);
    p = fmaf(p, f, 5.5504109e-2f);
    p = fmaf(p, f, 2.4022651e-1f);
    p = fmaf(p, f, 6.9314718e-1f);
    p = fmaf(p, f, 1.0f);
    int e = (int)fi;                // fi in [-126, 0]
    return p * __int_as_float((e + 127) << 23);
}

// ---------------- K1/K5: C[m,n] = X[m,:] . W[n,:] + bias[n] ------------------
// X: [4096,768] row-major, W: [768,768] row-major (so this is X @ W^T), both
// K-contiguous. 128x128 block tile, BK=8, 256 threads, 8x8 microtile.
__device__ __forceinline__ void gemm_nt_body(
    const float* __restrict__ X, const float* __restrict__ W,
    const float* __restrict__ bias, float* __restrict__ Y)
{
    __shared__ float As[8][128];
    __shared__ float Bs[8][128];
    const int t  = threadIdx.x;
    const int tx = t & 15, ty = t >> 4;
    const int bm = blockIdx.y * 128, bn = blockIdx.x * 128;
    const int arow = t >> 1, ac = (t & 1) * 4;

    float acc[8][8];
#pragma unroll
    for (int i = 0; i < 8; i++)
#pragma unroll
        for (int j = 0; j < 8; j++) acc[i][j] = 0.f;

    for (int k0 = 0; k0 < 768; k0 += 8) {
        float4 av = *(const float4*)(X + (bm + arow) * 768 + k0 + ac);
        float4 bv = *(const float4*)(W + (bn + arow) * 768 + k0 + ac);
        __syncthreads();
        As[ac + 0][arow] = av.x; As[ac + 1][arow] = av.y;
        As[ac + 2][arow] = av.z; As[ac + 3][arow] = av.w;
        Bs[ac + 0][arow] = bv.x; Bs[ac + 1][arow] = bv.y;
        Bs[ac + 2][arow] = bv.z; Bs[ac + 3][arow] = bv.w;
        __syncthreads();
#pragma unroll
        for (int kk = 0; kk < 8; kk++) {
            float a[8], b[8];
            *(float4*)(a)     = *(const float4*)&As[kk][ty * 8];
            *(float4*)(a + 4) = *(const float4*)&As[kk][ty * 8 + 4];
            *(float4*)(b)     = *(const float4*)&Bs[kk][tx * 8];
            *(float4*)(b + 4) = *(const float4*)&Bs[kk][tx * 8 + 4];
#pragma unroll
            for (int i = 0; i < 8; i++)
#pragma unroll
                for (int j = 0; j < 8; j++)
                    acc[i][j] = fmaf(a[i], b[j], acc[i][j]);
        }
    }

    float bb[8];
#pragma unroll
    for (int j = 0; j < 8; j++) bb[j] = bias[bn + tx * 8 + j];
#pragma unroll
    for (int i = 0; i < 8; i++) {
        float* yr = Y + (bm + ty * 8 + i) * 768 + bn + tx * 8;
        float4 o0 = make_float4(acc[i][0] + bb[0], acc[i][1] + bb[1],
                                acc[i][2] + bb[2], acc[i][3] + bb[3]);
        float4 o1 = make_float4(acc[i][4] + bb[4], acc[i][5] + bb[5],
                                acc[i][6] + bb[6], acc[i][7] + bb[7]);
        *(float4*)(yr)     = o0;
        *(float4*)(yr + 4) = o1;
    }
}

__global__ __launch_bounds__(256) void k_proj(
    const float* __restrict__ q, const float* __restrict__ k,
    const float* __restrict__ v, const float* __restrict__ Wq,
    const float* __restrict__ bq)
{
    const float* X = (blockIdx.z == 0) ? q : (blockIdx.z == 1) ? k : v;
    float* Y = (blockIdx.z == 0) ? g_qf : (blockIdx.z == 1) ? g_kf : g_vf;
    gemm_nt_body(X, Wq, bq, Y);
}

__global__ __launch_bounds__(256) void k_final(
    const float* __restrict__ Wf, const float* __restrict__ bf,
    float* __restrict__ out)
{
    gemm_nt_body(g_ctx, Wf, bf, out);
}

// ---------------- K2: raw logits  L0[b,h,q,k] = 0.125 * qh . kh -------------
// Per (b,h): [1024,64] x [1024,64]^T ("NT", K=64), rows strided by 768.
__global__ __launch_bounds__(256) void k_qk()
{
    __shared__ float As[8][128];
    __shared__ float Bs[8][128];
    const int bh = blockIdx.z;
    const int b = bh / HH, h = bh % HH;
    const float* Aq = g_qf + b * SS * DD + h * HDD;
    const float* Bk = g_kf + b * SS * DD + h * HDD;
    float* C = g_L0 + bh * SS * SS;

    const int t  = threadIdx.x;
    const int tx = t & 15, ty = t >> 4;
    const int bm = blockIdx.y * 128, bn = blockIdx.x * 128;
    const int arow = t >> 1, ac = (t & 1) * 4;

    float acc[8][8];
#pragma unroll
    for (int i = 0; i < 8; i++)
#pragma unroll
        for (int j = 0; j < 8; j++) acc[i][j] = 0.f;

    for (int k0 = 0; k0 < 64; k0 += 8) {
        float4 av = *(const float4*)(Aq + (bm + arow) * DD + k0 + ac);
        float4 bv = *(const float4*)(Bk + (bn + arow) * DD + k0 + ac);
        __syncthreads();
        As[ac + 0][arow] = av.x; As[ac + 1][arow] = av.y;
        As[ac + 2][arow] = av.z; As[ac + 3][arow] = av.w;
        Bs[ac + 0][arow] = bv.x; Bs[ac + 1][arow] = bv.y;
        Bs[ac + 2][arow] = bv.z; Bs[ac + 3][arow] = bv.w;
        __syncthreads();
#pragma unroll
        for (int kk = 0; kk < 8; kk++) {
            float a[8], bfr[8];
            *(float4*)(a)       = *(const float4*)&As[kk][ty * 8];
            *(float4*)(a + 4)   = *(const float4*)&As[kk][ty * 8 + 4];
            *(float4*)(bfr)     = *(const float4*)&Bs[kk][tx * 8];
            *(float4*)(bfr + 4) = *(const float4*)&Bs[kk][tx * 8 + 4];
#pragma unroll
            for (int i = 0; i < 8; i++)
#pragma unroll
                for (int j = 0; j < 8; j++)
                    acc[i][j] = fmaf(a[i], bfr[j], acc[i][j]);
        }
    }

#pragma unroll
    for (int i = 0; i < 8; i++) {
        float* cr = C + (bm + ty * 8 + i) * SS + bn + tx * 8;
        float4 o0 = make_float4(acc[i][0] * 0.125f, acc[i][1] * 0.125f,
                                acc[i][2] * 0.125f, acc[i][3] * 0.125f);
        float4 o1 = make_float4(acc[i][4] * 0.125f, acc[i][5] * 0.125f,
                                acc[i][6] * 0.125f, acc[i][7] * 0.125f);
        *(float4*)(cr)     = o0;
        *(float4*)(cr + 4) = o1;
    }
}

// ---------------- K3: fused Wl-mix -> softmax -> Wp-mix per (b,q) row --------
// Block = one (b,q); 256 threads x 4 k-columns each. All 12 heads of the row
// live in registers across the whole pipeline (one read of L0, one write of A).
__global__ __launch_bounds__(256) void k_softmix(
    const float* __restrict__ Wl, const float* __restrict__ bl,
    const float* __restrict__ Wp, const float* __restrict__ bp)
{
    __shared__ float sWl[144], sWp[144], sbl[12], sbp[12];
    __shared__ float red[12][8];
    __shared__ float sstat[12];   // broadcast rowmax, then 1/rowsum
    __shared__ float sinv[12];

    const int t = threadIdx.x;
    if (t < 144) { sWl[t] = Wl[t]; sWp[t] = Wp[t]; }
    if (t < 12)  { sbl[t] = bl[t]; sbp[t] = bp[t]; }
    __syncthreads();

    const int q = blockIdx.x, b = blockIdx.y;
    const int base = (b * HH) * SS * SS + q * SS;   // head-0 row offset

    // ---- Wl mix: L[g][c] = bl[g] + sum_h Wl[g,h] * L0[b,h,q,k] ----
    float L[12][4];
#pragma unroll
    for (int g = 0; g < 12; g++) {
        float bv = sbl[g];
        L[g][0] = bv; L[g][1] = bv; L[g][2] = bv; L[g][3] = bv;
    }
#pragma unroll
    for (int h = 0; h < 12; h++) {
        float4 r = ((const float4*)(g_L0 + base + h * SS * SS))[t];
#pragma unroll
        for (int g = 0; g < 12; g++) {
            float w = sWl[g * 12 + h];
            L[g][0] = fmaf(w, r.x, L[g][0]);
            L[g][1] = fmaf(w, r.y, L[g][1]);
            L[g][2] = fmaf(w, r.z, L[g][2]);
            L[g][3] = fmaf(w, r.w, L[g][3]);
        }
    }

    // ---- rowmax per g ----
    float mx[12];
#pragma unroll
    for (int g = 0; g < 12; g++)
        mx[g] = fmaxf(fmaxf(L[g][0], L[g][1]), fmaxf(L[g][2], L[g][3]));
#pragma unroll
    for (int o = 16; o; o >>= 1)
#pragma unroll
        for (int g = 0; g < 12; g++)
            mx[g] = fmaxf(mx[g], __shfl_xor_sync(0xffffffffu, mx[g], o));
    if ((t & 31) == 0)
#pragma unroll
        for (int g = 0; g < 12; g++) red[g][t >> 5] = mx[g];
    __syncthreads();
    if (t < 12) {
        float m = red[t][0];
#pragma unroll
        for (int w = 1; w < 8; w++) m = fmaxf(m, red[t][w]);
        sstat[t] = m;
    }
    __syncthreads();

    // ---- exp + rowsum ----
    float sm[12];
#pragma unroll
    for (int g = 0; g < 12; g++) {
        float m = sstat[g];
        float p0 = fexp(L[g][0] - m);
        float p1 = fexp(L[g][1] - m);
        float p2 = fexp(L[g][2] - m);
        float p3 = fexp(L[g][3] - m);
        L[g][0] = p0; L[g][1] = p1; L[g][2] = p2; L[g][3] = p3;
        sm[g] = (p0 + p1) + (p2 + p3);
    }
#pragma unroll
    for (int o = 16; o; o >>= 1)
#pragma unroll
        for (int g = 0; g < 12; g++)
            sm[g] += __shfl_xor_sync(0xffffffffu, sm[g], o);
    __syncthreads();                 // red reuse: prior readers are done
    if ((t & 31) == 0)
#pragma unroll
        for (int g = 0; g < 12; g++) red[g][t >> 5] = sm[g];
    __syncthreads();
    if (t < 12) {
        float s = red[t][0];
#pragma unroll
        for (int w = 1; w < 8; w++) s += red[t][w];
        sinv[t] = 1.0f / s;          // 12 divisions per block total
    }
    __syncthreads();

    // ---- normalize ----
#pragma unroll
    for (int h = 0; h < 12; h++) {
        float iv = sinv[h];
        L[h][0] *= iv; L[h][1] *= iv; L[h][2] *= iv; L[h][3] *= iv;
    }

    // ---- Wp mix + bp, write mixed attention A[b,g,q,k] ----
#pragma unroll
    for (int g = 0; g < 12; g++) {
        float bv = sbp[g];
        float a0 = bv, a1 = bv, a2 = bv, a3 = bv;
#pragma unroll
        for (int h = 0; h < 12; h++) {
            float w = sWp[g * 12 + h];
            a0 = fmaf(w, L[h][0], a0);
            a1 = fmaf(w, L[h][1], a1);
            a2 = fmaf(w, L[h][2], a2);
            a3 = fmaf(w, L[h][3], a3);
        }
        ((float4*)(g_A + base + g * SS * SS))[t] = make_float4(a0, a1, a2, a3);
    }
}

// ---------------- K4: ctx[b,q,g*64+e] = sum_k A[b,g,q,k] * vf[b,k,g*64+e] ---
// Per (b,g): 1024x64x1024 "NN" GEMM. 128x64 tile, BK=16, 256 thr, 8x4 micro.
__global__ __launch_bounds__(256) void k_av()
{
    __shared__ float As[16][128];
    __shared__ float Bs[16][64];
    const int bh = blockIdx.y;
    const int b = bh / HH, g = bh % HH;
    const float* A = g_A + bh * SS * SS;
    const float* V = g_vf + b * SS * DD + g * HDD;
    float* C = g_ctx + b * SS * DD + g * HDD;

    const int t  = threadIdx.x;
    const int tx = t & 15, ty = t >> 4;
    const int bm = blockIdx.x * 128;

    float acc[8][4];
#pragma unroll
    for (int i = 0; i < 8; i++)
#pragma unroll
        for (int j = 0; j < 4; j++) acc[i][j] = 0.f;

    for (int k0 = 0; k0 < SS; k0 += 16) {
        float4 av[2];
#pragma unroll
        for (int i = 0; i < 2; i++) {
            int c4 = ((t * 2 + i) & 3) << 2;
            av[i] = *(const float4*)(A + (bm + (t >> 1)) * SS + k0 + c4);
        }
        float4 bv = *(const float4*)(V + (k0 + (t >> 4)) * DD + ((t & 15) << 2));
        __syncthreads();
#pragma unroll
        for (int i = 0; i < 2; i++) {
            int c4 = ((t * 2 + i) & 3) << 2;
            int r = t >> 1;
            As[c4 + 0][r] = av[i].x; As[c4 + 1][r] = av[i].y;
            As[c4 + 2][r] = av[i].z; As[c4 + 3][r] = av[i].w;
        }
        *(float4*)&Bs[t >> 4][(t & 15) << 2] = bv;
        __syncthreads();
#pragma unroll
        for (int kk = 0; kk < 16; kk++) {
            float a[8], b4[4];
            *(float4*)(a)     = *(const float4*)&As[kk][ty * 8];
            *(float4*)(a + 4) = *(const float4*)&As[kk][ty * 8 + 4];
            *(float4*)(b4)    = *(const float4*)&Bs[kk][tx * 4];
#pragma unroll
            for (int i = 0; i < 8; i++)
#pragma unroll
                for (int j = 0; j < 4; j++)
                    acc[i][j] = fmaf(a[i], b4[j], acc[i][j]);
        }
    }

#pragma unroll
    for (int i = 0; i < 8; i++) {
        *(float4*)(C + (bm + ty * 8 + i) * DD + tx * 4) =
            make_float4(acc[i][0], acc[i][1], acc[i][2], acc[i][3]);
    }
}

// ---------------- launch ------------------------------------------------------
extern "C" void kernel_launch(void* const* d_in, const int* in_sizes, int n_in,
                              void* d_out, int out_size)
{
    const float* q  = (const float*)d_in[0];
    const float* k  = (const float*)d_in[1];
    const float* v  = (const float*)d_in[2];
    const float* Wq = (const float*)d_in[3];
    const float* bq = (const float*)d_in[4];
    const float* Wl = (const float*)d_in[5];
    const float* bl = (const float*)d_in[6];
    const float* Wp = (const float*)d_in[7];
    const float* bp = (const float*)d_in[8];
    const float* Wf = (const float*)d_in[9];
    const float* bf = (const float*)d_in[10];
    float* out = (float*)d_out;

    k_proj   <<<dim3(6, 32, 3),  256>>>(q, k, v, Wq, bq);
    k_qk     <<<dim3(8, 8, 48),  256>>>();
    k_softmix<<<dim3(1024, 4),   256>>>(Wl, bl, Wp, bp);
    k_av     <<<dim3(8, 48),     256>>>();
    k_final  <<<dim3(6, 32),     256>>>(Wf, bf, out);
}